// round 11
// baseline (speedup 1.0000x reference)
#include <cuda_runtime.h>
#include <cstdint>

#define N_BOX     8192
#define MAX_KEEP  256
#define MIN_SCORE 0.3f
#define NMS_THR   0.3f
#define NT        1024
#define NBKT      4096
#define NCHUNK    128          // 64-bit words per mask row (8192/64)
#define FULL      0xFFFFFFFFu

// ---------------- global scratch (static __device__, no allocation) ----------------
__device__ unsigned long long g_key[N_BOX];        // sorted keys (~score_bits, idx)
__device__ float4             g_cbox[N_BOX];       // sorted xyxy boxes
__device__ unsigned long long g_mask[N_BOX * NCHUNK];  // 8 MB suppression bitmask
__device__ int                g_nval;

// ================= kernel A: bucket sort (exact stable descending) — R9 proven =================
extern __shared__ unsigned char dynsmem[];

__global__ void __launch_bounds__(NT, 1)
sort_kernel(const float* __restrict__ score, const float* __restrict__ box)
{
    unsigned long long* s_key = (unsigned long long*)dynsmem;          // 64 KB
    unsigned int*       s_cnt = (unsigned int*)(dynsmem + 65536);      // 16 KB
    unsigned int*       s_off = (unsigned int*)(dynsmem + 81920);      // 16 KB
    __shared__ unsigned int s_wsum[32];
    __shared__ int s_nvalid;

    const int tid  = threadIdx.x;
    const int lane = tid & 31;
    const int wid  = tid >> 5;

    for (int i = tid; i < NBKT; i += NT) s_cnt[i] = 0;
    __syncthreads();

    float sc[8]; int bk[8];
    #pragma unroll
    for (int k = 0; k < 8; k++) {
        int i = tid + k * NT;
        float s = score[i];
        sc[k] = s;
        int b = -1;
        if (s >= MIN_SCORE) {
            b = 4095 - min(4095, (int)(s * 4096.0f));   // score desc -> bucket asc (monotone)
            atomicAdd(&s_cnt[b], 1u);
        }
        bk[k] = b;
    }
    __syncthreads();

    unsigned int c0 = s_cnt[tid*4+0], c1 = s_cnt[tid*4+1], c2 = s_cnt[tid*4+2], c3 = s_cnt[tid*4+3];
    unsigned int tsum = c0 + c1 + c2 + c3;
    unsigned int p = tsum;
    #pragma unroll
    for (int d = 1; d < 32; d <<= 1) {
        unsigned int v = __shfl_up_sync(FULL, p, d);
        if (lane >= d) p += v;
    }
    if (lane == 31) s_wsum[wid] = p;
    __syncthreads();
    if (wid == 0) {
        unsigned int w = s_wsum[lane];
        unsigned int q = w;
        #pragma unroll
        for (int d = 1; d < 32; d <<= 1) {
            unsigned int v = __shfl_up_sync(FULL, q, d);
            if (lane >= d) q += v;
        }
        s_wsum[lane] = q - w;
        if (lane == 31) s_nvalid = (int)q;
    }
    __syncthreads();
    unsigned int basep = s_wsum[wid] + (p - tsum);
    s_off[tid*4+0] = basep;
    s_off[tid*4+1] = basep + c0;
    s_off[tid*4+2] = basep + c0 + c1;
    s_off[tid*4+3] = basep + c0 + c1 + c2;
    __syncthreads();

    #pragma unroll
    for (int k = 0; k < 8; k++) {
        if (bk[k] >= 0) {
            int i = tid + k * NT;
            unsigned int pos = atomicAdd(&s_off[bk[k]], 1u);
            s_key[pos] = ((unsigned long long)(~__float_as_uint(sc[k])) << 32) | (unsigned int)i;
        }
    }
    __syncthreads();

    // intra-bucket insertion sort on full u64 key (exact total order)
    for (int b = tid; b < NBKT; b += NT) {
        int lo = b ? (int)s_off[b-1] : 0;
        int hi = (int)s_off[b];
        for (int i = lo + 1; i < hi; i++) {
            unsigned long long v = s_key[i];
            int j = i - 1;
            while (j >= lo && s_key[j] > v) { s_key[j+1] = s_key[j]; j--; }
            s_key[j+1] = v;
        }
    }
    __syncthreads();

    const int nval = s_nvalid;
    for (int c = tid; c < nval; c += NT) {
        unsigned long long key = s_key[c];
        g_key[c] = key;
        int idx = (int)(key & 0xFFFFFFFFull);
        float4 b4 = *(const float4*)(box + idx * 16);
        float hw = b4.z * 0.5f, hh = b4.w * 0.5f;
        g_cbox[c] = make_float4(b4.x - hw, b4.y - hh, b4.x + hw, b4.y + hh);
    }
    if (tid == 0) g_nval = nval;
}

// ================= kernel B: suppression bitmask matrix — R9 proven =================
// block: 256 threads = 256 rows; grid (32, 128): (row tile, col word)
// Division-free threshold test, bit-exact vs reference (guarded multiply-compare with
// exact-division fallback only inside a +-1e-6 relative window around the threshold).
__global__ void __launch_bounds__(256)
mask_kernel()
{
    const int tj = blockIdx.y;               // col word 0..127
    const int i0 = blockIdx.x * 256;         // row tile base
    const int nval = g_nval;
    if (i0 >= nval) return;
    if (tj * 64 + 63 <= i0) return;          // whole tile has j <= all rows -> unread

    __shared__ float4 cb[64];
    __shared__ float  car[64];
    const int t = threadIdx.x;
    if (t < 64) {
        int j = tj * 64 + t;
        float4 b = (j < nval) ? g_cbox[j] : make_float4(0,0,0,0);
        cb[t]  = b;
        car[t] = (b.z - b.x) * (b.w - b.y);
    }
    __syncthreads();

    const int i = i0 + t;
    if (i >= nval) return;
    float4 B  = g_cbox[i];
    float  AR = (B.z - B.x) * (B.w - B.y);

    const int qlo  = max(0, i + 1 - tj * 64);             // strict j > i
    const int qmax = min(64, nval - tj * 64);
    unsigned long long w = 0;
    #pragma unroll 4
    for (int q = qlo; q < qmax; q++) {
        float4 b = cb[q];
        float lx = fmaxf(B.x, b.x), ly = fmaxf(B.y, b.y);
        float rx = fminf(B.z, b.z), ry = fminf(B.w, b.w);
        float inter = fmaxf(rx - lx, 0.0f) * fmaxf(ry - ly, 0.0f);
        float denom = ((AR + car[q]) - inter) + 1e-9f;    // reference association order
        float thr   = denom * NMS_THR;
        bool hit;
        if (inter > thr * 1.000001f)      hit = true;     // definitely above threshold
        else if (inter < thr * 0.999999f) hit = false;    // definitely below
        else                              hit = (inter / denom) > NMS_THR;  // exact (rare)
        if (hit) w |= 1ull << q;
    }
    g_mask[i * NCHUNK + tj] = w;
}

// ================= kernel C: warp-0 sweep, barrier-free chunk loop =================
// dynamic smem: diag[8192] u64 (64 KB) = word (i/64) of mask row i, i.e. the 64x64
// diagonal suppression block of each chunk, preloaded once by all 256 threads.
__global__ void __launch_bounds__(256, 1)
sweep_kernel(const float* __restrict__ box, float* __restrict__ out)
{
    unsigned long long* diag = (unsigned long long*)dynsmem;   // 64 KB

    __shared__ unsigned long long rem[NCHUNK];
    __shared__ int   klist[64];
    __shared__ int   keptidx[MAX_KEEP];
    __shared__ int   s_kc;
    __shared__ int   s_orig[MAX_KEEP];

    const int tid    = threadIdx.x;
    const int lane   = tid & 31;
    const int wid    = tid >> 5;
    const int nval   = g_nval;
    const int nchunk = (nval + 63) >> 6;

    // preload all diagonal words + clear rem
    for (int i = tid; i < nval; i += 256)
        diag[i] = g_mask[i * NCHUNK + (i >> 6)];
    if (tid < NCHUNK) rem[tid] = 0ull;
    if (tid == 0) s_kc = 0;
    __syncthreads();

    // ---- chunk loop: warp 0 only, __syncwarp-synchronized ----
    if (wid == 0) {
        int kc = 0;
        for (int c = 0; c < nchunk && kc < MAX_KEEP; c++) {
            int n = 0;
            if (lane == 0) {
                int rembits = nval - c * 64;
                unsigned long long validw = (rembits >= 64) ? ~0ull : ((1ull << rembits) - 1ull);
                unsigned long long alive = validw & ~rem[c];
                const unsigned long long* db = diag + c * 64;
                while (alive && kc < MAX_KEEP) {
                    int t = __ffsll((long long)alive) - 1;
                    keptidx[kc++] = c * 64 + t;
                    klist[n++] = t;
                    alive &= ~db[t];
                    alive &= ~(1ull << t);
                }
            }
            n  = __shfl_sync(FULL, n, 0);
            kc = __shfl_sync(FULL, kc, 0);
            if (n) {
                __syncwarp(FULL);                      // klist visible to all lanes
                const int base = c * 64;
                for (int w = c + 1 + lane; w < nchunk; w += 32) {
                    unsigned long long acc = 0;
                    for (int q = 0; q < n; q++)
                        acc |= g_mask[(base + klist[q]) * NCHUNK + w];
                    rem[w] |= acc;
                }
                __syncwarp(FULL);                      // rem visible before next resolve
            }
        }
        if (lane == 0) s_kc = kc;
    }
    __syncthreads();

    // ---------------- outputs (all 256 threads) ----------------
    // layout: [0,256) score | [256,4352) box (256x16) | [4352,4608) valid
    const int kc = s_kc;
    for (int k = tid; k < MAX_KEEP; k += 256) {
        if (k < kc) {
            unsigned long long key = g_key[keptidx[k]];
            s_orig[k]     = (int)(key & 0xFFFFFFFFull);
            out[k]        = __uint_as_float(~(unsigned int)(key >> 32));
            out[4352 + k] = 1.0f;
        } else {
            out[k]        = 0.0f;
            out[4352 + k] = 0.0f;
        }
    }
    __syncthreads();
    for (int e = tid; e < MAX_KEEP * 16; e += 256) {
        int k = e >> 4, c = e & 15;
        out[256 + e] = (k < kc) ? box[s_orig[k] * 16 + c] : 0.0f;
    }
}

// ---------------- launch ----------------
extern "C" void kernel_launch(void* const* d_in, const int* in_sizes, int n_in,
                              void* d_out, int out_size) {
    const float* score = (const float*)d_in[0];
    const float* box   = (const float*)d_in[1];
    float* out = (float*)d_out;

    const int dynA = 98304;   // 64K keys + 16K hist + 16K offsets
    cudaFuncSetAttribute(sort_kernel,
                         cudaFuncAttributeMaxDynamicSharedMemorySize, dynA);
    const int dynC = 65536;   // 64K diag
    cudaFuncSetAttribute(sweep_kernel,
                         cudaFuncAttributeMaxDynamicSharedMemorySize, dynC);

    sort_kernel<<<1, NT, dynA>>>(score, box);
    mask_kernel<<<dim3(32, 128), 256>>>();
    sweep_kernel<<<1, 256, dynC>>>(box, out);
}

// round 12
// speedup vs baseline: 1.4793x; 1.4793x over previous
#include <cuda_runtime.h>
#include <cstdint>

#define N_BOX     8192
#define MAX_KEEP  256
#define MIN_SCORE 0.3f
#define NMS_THR   0.3f
#define NT        1024
#define NBKT      4096
#define NCHUNK    128          // 64-bit words per mask row (8192/64)
#define FULL      0xFFFFFFFFu

// ---------------- global scratch (static __device__, no allocation) ----------------
__device__ unsigned long long g_key[N_BOX];        // sorted keys (~score_bits, idx)
__device__ float4             g_cbox[N_BOX];       // sorted xyxy boxes
__device__ unsigned long long g_mask[N_BOX * NCHUNK];  // 8 MB suppression bitmask
__device__ int                g_nval;

// ================= kernel A: bucket sort (exact stable descending) — R9 proven =================
extern __shared__ unsigned char dynsmem[];

__global__ void __launch_bounds__(NT, 1)
sort_kernel(const float* __restrict__ score, const float* __restrict__ box)
{
    unsigned long long* s_key = (unsigned long long*)dynsmem;          // 64 KB
    unsigned int*       s_cnt = (unsigned int*)(dynsmem + 65536);      // 16 KB
    unsigned int*       s_off = (unsigned int*)(dynsmem + 81920);      // 16 KB
    __shared__ unsigned int s_wsum[32];
    __shared__ int s_nvalid;

    const int tid  = threadIdx.x;
    const int lane = tid & 31;
    const int wid  = tid >> 5;

    for (int i = tid; i < NBKT; i += NT) s_cnt[i] = 0;
    __syncthreads();

    float sc[8]; int bk[8];
    #pragma unroll
    for (int k = 0; k < 8; k++) {
        int i = tid + k * NT;
        float s = score[i];
        sc[k] = s;
        int b = -1;
        if (s >= MIN_SCORE) {
            b = 4095 - min(4095, (int)(s * 4096.0f));   // score desc -> bucket asc (monotone)
            atomicAdd(&s_cnt[b], 1u);
        }
        bk[k] = b;
    }
    __syncthreads();

    unsigned int c0 = s_cnt[tid*4+0], c1 = s_cnt[tid*4+1], c2 = s_cnt[tid*4+2], c3 = s_cnt[tid*4+3];
    unsigned int tsum = c0 + c1 + c2 + c3;
    unsigned int p = tsum;
    #pragma unroll
    for (int d = 1; d < 32; d <<= 1) {
        unsigned int v = __shfl_up_sync(FULL, p, d);
        if (lane >= d) p += v;
    }
    if (lane == 31) s_wsum[wid] = p;
    __syncthreads();
    if (wid == 0) {
        unsigned int w = s_wsum[lane];
        unsigned int q = w;
        #pragma unroll
        for (int d = 1; d < 32; d <<= 1) {
            unsigned int v = __shfl_up_sync(FULL, q, d);
            if (lane >= d) q += v;
        }
        s_wsum[lane] = q - w;
        if (lane == 31) s_nvalid = (int)q;
    }
    __syncthreads();
    unsigned int basep = s_wsum[wid] + (p - tsum);
    s_off[tid*4+0] = basep;
    s_off[tid*4+1] = basep + c0;
    s_off[tid*4+2] = basep + c0 + c1;
    s_off[tid*4+3] = basep + c0 + c1 + c2;
    __syncthreads();

    #pragma unroll
    for (int k = 0; k < 8; k++) {
        if (bk[k] >= 0) {
            int i = tid + k * NT;
            unsigned int pos = atomicAdd(&s_off[bk[k]], 1u);
            s_key[pos] = ((unsigned long long)(~__float_as_uint(sc[k])) << 32) | (unsigned int)i;
        }
    }
    __syncthreads();

    // intra-bucket insertion sort on full u64 key (exact total order)
    for (int b = tid; b < NBKT; b += NT) {
        int lo = b ? (int)s_off[b-1] : 0;
        int hi = (int)s_off[b];
        for (int i = lo + 1; i < hi; i++) {
            unsigned long long v = s_key[i];
            int j = i - 1;
            while (j >= lo && s_key[j] > v) { s_key[j+1] = s_key[j]; j--; }
            s_key[j+1] = v;
        }
    }
    __syncthreads();

    const int nval = s_nvalid;
    for (int c = tid; c < nval; c += NT) {
        unsigned long long key = s_key[c];
        g_key[c] = key;
        int idx = (int)(key & 0xFFFFFFFFull);
        float4 b4 = *(const float4*)(box + idx * 16);
        float hw = b4.z * 0.5f, hh = b4.w * 0.5f;
        g_cbox[c] = make_float4(b4.x - hw, b4.y - hh, b4.x + hw, b4.y + hh);
    }
    if (tid == 0) g_nval = nval;
}

// ================= kernel B: suppression bitmask matrix — R9 proven =================
// block: 256 threads = 256 rows; grid (32, 128): (row tile, col word)
// Division-free threshold test, bit-exact vs reference (guarded multiply-compare with
// exact-division fallback only inside a +-1e-6 relative window around the threshold).
__global__ void __launch_bounds__(256)
mask_kernel()
{
    const int tj = blockIdx.y;               // col word 0..127
    const int i0 = blockIdx.x * 256;         // row tile base
    const int nval = g_nval;
    if (i0 >= nval) return;
    if (tj * 64 + 63 <= i0) return;          // whole tile has j <= all rows -> unread

    __shared__ float4 cb[64];
    __shared__ float  car[64];
    const int t = threadIdx.x;
    if (t < 64) {
        int j = tj * 64 + t;
        float4 b = (j < nval) ? g_cbox[j] : make_float4(0,0,0,0);
        cb[t]  = b;
        car[t] = (b.z - b.x) * (b.w - b.y);
    }
    __syncthreads();

    const int i = i0 + t;
    if (i >= nval) return;
    float4 B  = g_cbox[i];
    float  AR = (B.z - B.x) * (B.w - B.y);

    const int qlo  = max(0, i + 1 - tj * 64);             // strict j > i
    const int qmax = min(64, nval - tj * 64);
    unsigned long long w = 0;
    #pragma unroll 4
    for (int q = qlo; q < qmax; q++) {
        float4 b = cb[q];
        float lx = fmaxf(B.x, b.x), ly = fmaxf(B.y, b.y);
        float rx = fminf(B.z, b.z), ry = fminf(B.w, b.w);
        float inter = fmaxf(rx - lx, 0.0f) * fmaxf(ry - ly, 0.0f);
        float denom = ((AR + car[q]) - inter) + 1e-9f;    // reference association order
        float thr   = denom * NMS_THR;
        bool hit;
        if (inter > thr * 1.000001f)      hit = true;     // definitely above threshold
        else if (inter < thr * 0.999999f) hit = false;    // definitely below
        else                              hit = (inter / denom) > NMS_THR;  // exact (rare)
        if (hit) w |= 1ull << q;
    }
    g_mask[i * NCHUNK + tj] = w;
}

// ================= kernel C: sweep with kept-chunk-only barrier rounds =================
// dynamic smem: diag[8192] u64 (64 KB) = word (i>>6) of mask row i (the 64x64 diagonal
// block of every chunk), preloaded once by all 256 threads. Thread 0 privately skips
// alive-empty chunks (pure smem reads); the block synchronizes only when a chunk
// actually keeps boxes and their rows must be propagated (256-wide coalesced loads).
__global__ void __launch_bounds__(256, 1)
sweep_kernel(const float* __restrict__ box, float* __restrict__ out)
{
    unsigned long long* diag = (unsigned long long*)dynsmem;   // 64 KB

    __shared__ unsigned long long rem[NCHUNK];
    __shared__ int klist[64];
    __shared__ int keptidx[MAX_KEEP];
    __shared__ int s_orig[MAX_KEEP];
    __shared__ int s_c, s_n, s_kc, s_next;

    const int tid    = threadIdx.x;
    const int nval   = g_nval;
    const int nchunk = (nval + 63) >> 6;

    // one-time preload of all diagonal words + clear rem
    for (int i = tid; i < nval; i += 256)
        diag[i] = g_mask[i * NCHUNK + (i >> 6)];
    if (tid < NCHUNK) rem[tid] = 0ull;
    if (tid == 0) { s_kc = 0; s_next = 0; }
    __syncthreads();

    while (true) {
        // ---- thread 0: scan forward, skipping alive-empty chunks at smem cost ----
        if (tid == 0) {
            int c  = s_next;
            int kc = s_kc;
            int n  = 0;
            while (c < nchunk) {
                int rembits = nval - c * 64;
                unsigned long long validw = (rembits >= 64) ? ~0ull : ((1ull << rembits) - 1ull);
                unsigned long long alive = validw & ~rem[c];
                if (!alive) { c++; continue; }
                const unsigned long long* db = diag + c * 64;
                while (alive && kc < MAX_KEEP) {
                    int t = __ffsll((long long)alive) - 1;
                    keptidx[kc++] = c * 64 + t;
                    klist[n++] = t;
                    alive &= ~db[t];
                    alive &= ~(1ull << t);
                }
                break;
            }
            // if cap reached, nothing after this will be resolved -> no propagation needed
            if (kc >= MAX_KEEP) n = 0;
            s_c = c; s_n = n; s_kc = kc; s_next = c + 1;
        }
        __syncthreads();

        const int n = s_n;
        if (n == 0) break;                    // end of list or kept cap reached

        // ---- propagate the new kept rows into rem (256-wide, coalesced) ----
        const int c    = s_c;
        const int base = c * 64;
        for (int w = c + 1 + tid; w < nchunk; w += 256) {
            unsigned long long acc = 0;
            for (int q = 0; q < n; q++)
                acc |= g_mask[(base + klist[q]) * NCHUNK + w];
            rem[w] |= acc;
        }
        __syncthreads();                      // rem complete before next scan
    }

    // ---------------- outputs ----------------
    // layout: [0,256) score | [256,4352) box (256x16) | [4352,4608) valid
    const int kc = s_kc;
    for (int k = tid; k < MAX_KEEP; k += 256) {
        if (k < kc) {
            unsigned long long key = g_key[keptidx[k]];
            s_orig[k]     = (int)(key & 0xFFFFFFFFull);
            out[k]        = __uint_as_float(~(unsigned int)(key >> 32));
            out[4352 + k] = 1.0f;
        } else {
            out[k]        = 0.0f;
            out[4352 + k] = 0.0f;
        }
    }
    __syncthreads();
    for (int e = tid; e < MAX_KEEP * 16; e += 256) {
        int k = e >> 4, c = e & 15;
        out[256 + e] = (k < kc) ? box[s_orig[k] * 16 + c] : 0.0f;
    }
}

// ---------------- launch ----------------
extern "C" void kernel_launch(void* const* d_in, const int* in_sizes, int n_in,
                              void* d_out, int out_size) {
    const float* score = (const float*)d_in[0];
    const float* box   = (const float*)d_in[1];
    float* out = (float*)d_out;

    const int dynA = 98304;   // 64K keys + 16K hist + 16K offsets
    cudaFuncSetAttribute(sort_kernel,
                         cudaFuncAttributeMaxDynamicSharedMemorySize, dynA);
    const int dynC = 65536;   // 64K diag
    cudaFuncSetAttribute(sweep_kernel,
                         cudaFuncAttributeMaxDynamicSharedMemorySize, dynC);

    sort_kernel<<<1, NT, dynA>>>(score, box);
    mask_kernel<<<dim3(32, 128), 256>>>();
    sweep_kernel<<<1, 256, dynC>>>(box, out);
}

// round 14
// speedup vs baseline: 1.6461x; 1.1128x over previous
#include <cuda_runtime.h>
#include <cstdint>

#define N_BOX     8192
#define MAX_KEEP  256
#define MIN_SCORE 0.3f
#define NMS_THR   0.3f
#define NT        1024
#define NBKT      4096
#define NCHUNK    128          // 64-bit words per mask row (8192/64)
#define FULL      0xFFFFFFFFu

// ---------------- global scratch (static __device__, no allocation) ----------------
__device__ unsigned long long g_key[N_BOX];        // sorted keys (~score_bits, idx)
__device__ float4             g_cbox[N_BOX];       // sorted xyxy boxes
__device__ unsigned long long g_mask[N_BOX * NCHUNK];  // 8 MB suppression bitmask
__device__ unsigned long long g_diag[N_BOX];       // compact diagonal words (coalesced)
__device__ int                g_nval;

// ================= kernel A: bucket sort (exact stable descending) — R9 proven =================
extern __shared__ unsigned char dynsmem[];

__global__ void __launch_bounds__(NT, 1)
sort_kernel(const float* __restrict__ score, const float* __restrict__ box)
{
    unsigned long long* s_key = (unsigned long long*)dynsmem;          // 64 KB
    unsigned int*       s_cnt = (unsigned int*)(dynsmem + 65536);      // 16 KB
    unsigned int*       s_off = (unsigned int*)(dynsmem + 81920);      // 16 KB
    __shared__ unsigned int s_wsum[32];
    __shared__ int s_nvalid;

    const int tid  = threadIdx.x;
    const int lane = tid & 31;
    const int wid  = tid >> 5;

    for (int i = tid; i < NBKT; i += NT) s_cnt[i] = 0;
    __syncthreads();

    float sc[8]; int bk[8];
    #pragma unroll
    for (int k = 0; k < 8; k++) {
        int i = tid + k * NT;
        float s = score[i];
        sc[k] = s;
        int b = -1;
        if (s >= MIN_SCORE) {
            b = 4095 - min(4095, (int)(s * 4096.0f));   // score desc -> bucket asc (monotone)
            atomicAdd(&s_cnt[b], 1u);
        }
        bk[k] = b;
    }
    __syncthreads();

    unsigned int c0 = s_cnt[tid*4+0], c1 = s_cnt[tid*4+1], c2 = s_cnt[tid*4+2], c3 = s_cnt[tid*4+3];
    unsigned int tsum = c0 + c1 + c2 + c3;
    unsigned int p = tsum;
    #pragma unroll
    for (int d = 1; d < 32; d <<= 1) {
        unsigned int v = __shfl_up_sync(FULL, p, d);
        if (lane >= d) p += v;
    }
    if (lane == 31) s_wsum[wid] = p;
    __syncthreads();
    if (wid == 0) {
        unsigned int w = s_wsum[lane];
        unsigned int q = w;
        #pragma unroll
        for (int d = 1; d < 32; d <<= 1) {
            unsigned int v = __shfl_up_sync(FULL, q, d);
            if (lane >= d) q += v;
        }
        s_wsum[lane] = q - w;
        if (lane == 31) s_nvalid = (int)q;
    }
    __syncthreads();
    unsigned int basep = s_wsum[wid] + (p - tsum);
    s_off[tid*4+0] = basep;
    s_off[tid*4+1] = basep + c0;
    s_off[tid*4+2] = basep + c0 + c1;
    s_off[tid*4+3] = basep + c0 + c1 + c2;
    __syncthreads();

    #pragma unroll
    for (int k = 0; k < 8; k++) {
        if (bk[k] >= 0) {
            int i = tid + k * NT;
            unsigned int pos = atomicAdd(&s_off[bk[k]], 1u);
            s_key[pos] = ((unsigned long long)(~__float_as_uint(sc[k])) << 32) | (unsigned int)i;
        }
    }
    __syncthreads();

    // intra-bucket insertion sort on full u64 key (exact total order)
    for (int b = tid; b < NBKT; b += NT) {
        int lo = b ? (int)s_off[b-1] : 0;
        int hi = (int)s_off[b];
        for (int i = lo + 1; i < hi; i++) {
            unsigned long long v = s_key[i];
            int j = i - 1;
            while (j >= lo && s_key[j] > v) { s_key[j+1] = s_key[j]; j--; }
            s_key[j+1] = v;
        }
    }
    __syncthreads();

    const int nval = s_nvalid;
    for (int c = tid; c < nval; c += NT) {
        unsigned long long key = s_key[c];
        g_key[c] = key;
        int idx = (int)(key & 0xFFFFFFFFull);
        float4 b4 = *(const float4*)(box + idx * 16);
        float hw = b4.z * 0.5f, hh = b4.w * 0.5f;
        g_cbox[c] = make_float4(b4.x - hw, b4.y - hh, b4.x + hw, b4.y + hh);
    }
    if (tid == 0) g_nval = nval;
}

// ================= kernel B: suppression bitmask matrix — R9 proven (+ diag store) =================
// block: 256 threads = 256 rows; grid (32, 128): (row tile, col word)
// Division-free threshold test, bit-exact vs reference (guarded multiply-compare with
// exact-division fallback only inside a +-1e-6 relative window around the threshold).
__global__ void __launch_bounds__(256)
mask_kernel()
{
    const int tj = blockIdx.y;               // col word 0..127
    const int i0 = blockIdx.x * 256;         // row tile base
    const int nval = g_nval;
    if (i0 >= nval) return;
    if (tj * 64 + 63 <= i0) return;          // whole tile has j <= all rows -> unread

    __shared__ float4 cb[64];
    __shared__ float  car[64];
    const int t = threadIdx.x;
    if (t < 64) {
        int j = tj * 64 + t;
        float4 b = (j < nval) ? g_cbox[j] : make_float4(0,0,0,0);
        cb[t]  = b;
        car[t] = (b.z - b.x) * (b.w - b.y);
    }
    __syncthreads();

    const int i = i0 + t;
    if (i >= nval) return;
    float4 B  = g_cbox[i];
    float  AR = (B.z - B.x) * (B.w - B.y);

    const int qlo  = max(0, i + 1 - tj * 64);             // strict j > i
    const int qmax = min(64, nval - tj * 64);
    unsigned long long w = 0;
    #pragma unroll 4
    for (int q = qlo; q < qmax; q++) {
        float4 b = cb[q];
        float lx = fmaxf(B.x, b.x), ly = fmaxf(B.y, b.y);
        float rx = fminf(B.z, b.z), ry = fminf(B.w, b.w);
        float inter = fmaxf(rx - lx, 0.0f) * fmaxf(ry - ly, 0.0f);
        float denom = ((AR + car[q]) - inter) + 1e-9f;    // reference association order
        float thr   = denom * NMS_THR;
        bool hit;
        if (inter > thr * 1.000001f)      hit = true;     // definitely above threshold
        else if (inter < thr * 0.999999f) hit = false;    // definitely below
        else                              hit = (inter / denom) > NMS_THR;  // exact (rare)
        if (hit) w |= 1ull << q;
    }
    g_mask[i * NCHUNK + tj] = w;
    if (tj == (i >> 6)) g_diag[i] = w;       // compact diagonal copy (coalesced sweep preload)
}

// ================= kernel C: skip-empty sweep with coalesced diag preload =================
// dynamic smem: diag[8192] u64 (64 KB), preloaded from the COMPACT g_diag array
// (contiguous, coalesced). Thread 0 privately skips alive-empty chunks at smem cost;
// the block synchronizes only when a chunk keeps boxes (256-wide coalesced propagation).
__global__ void __launch_bounds__(256, 1)
sweep_kernel(const float* __restrict__ box, float* __restrict__ out)
{
    unsigned long long* diag = (unsigned long long*)dynsmem;   // 64 KB

    __shared__ unsigned long long rem[NCHUNK];
    __shared__ int klist[64];
    __shared__ int keptidx[MAX_KEEP];
    __shared__ int s_orig[MAX_KEEP];
    __shared__ int s_c, s_n, s_kc, s_next;

    const int tid    = threadIdx.x;
    const int nval   = g_nval;
    const int nchunk = (nval + 63) >> 6;

    // coalesced one-time preload of all diagonal words + clear rem
    for (int i = tid; i < nval; i += 256)
        diag[i] = g_diag[i];
    if (tid < NCHUNK) rem[tid] = 0ull;
    if (tid == 0) { s_kc = 0; s_next = 0; }
    __syncthreads();

    while (true) {
        // ---- thread 0: scan forward, skipping alive-empty chunks at smem cost ----
        if (tid == 0) {
            int c  = s_next;
            int kc = s_kc;
            int n  = 0;
            while (c < nchunk) {
                int rembits = nval - c * 64;
                unsigned long long validw = (rembits >= 64) ? ~0ull : ((1ull << rembits) - 1ull);
                unsigned long long alive = validw & ~rem[c];
                if (!alive) { c++; continue; }
                const unsigned long long* db = diag + c * 64;
                while (alive && kc < MAX_KEEP) {
                    int t = __ffsll((long long)alive) - 1;
                    keptidx[kc++] = c * 64 + t;
                    klist[n++] = t;
                    alive &= ~db[t];
                    alive &= ~(1ull << t);
                }
                break;
            }
            // if cap reached, nothing after this will be resolved -> no propagation needed
            if (kc >= MAX_KEEP) n = 0;
            s_c = c; s_n = n; s_kc = kc; s_next = c + 1;
        }
        __syncthreads();

        const int n = s_n;
        if (n == 0) break;                    // end of list or kept cap reached

        // ---- propagate the new kept rows into rem (256-wide, coalesced) ----
        const int c    = s_c;
        const int base = c * 64;
        for (int w = c + 1 + tid; w < nchunk; w += 256) {
            unsigned long long acc = 0;
            for (int q = 0; q < n; q++)
                acc |= g_mask[(base + klist[q]) * NCHUNK + w];
            rem[w] |= acc;
        }
        __syncthreads();                      // rem complete before next scan
    }

    // ---------------- outputs ----------------
    // layout: [0,256) score | [256,4352) box (256x16) | [4352,4608) valid
    const int kc = s_kc;
    for (int k = tid; k < MAX_KEEP; k += 256) {
        if (k < kc) {
            unsigned long long key = g_key[keptidx[k]];
            s_orig[k]     = (int)(key & 0xFFFFFFFFull);
            out[k]        = __uint_as_float(~(unsigned int)(key >> 32));
            out[4352 + k] = 1.0f;
        } else {
            out[k]        = 0.0f;
            out[4352 + k] = 0.0f;
        }
    }
    __syncthreads();
    for (int e = tid; e < MAX_KEEP * 16; e += 256) {
        int k = e >> 4, c = e & 15;
        out[256 + e] = (k < kc) ? box[s_orig[k] * 16 + c] : 0.0f;
    }
}

// ---------------- launch ----------------
extern "C" void kernel_launch(void* const* d_in, const int* in_sizes, int n_in,
                              void* d_out, int out_size) {
    const float* score = (const float*)d_in[0];
    const float* box   = (const float*)d_in[1];
    float* out = (float*)d_out;

    const int dynA = 98304;   // 64K keys + 16K hist + 16K offsets
    cudaFuncSetAttribute(sort_kernel,
                         cudaFuncAttributeMaxDynamicSharedMemorySize, dynA);
    const int dynC = 65536;   // 64K diag
    cudaFuncSetAttribute(sweep_kernel,
                         cudaFuncAttributeMaxDynamicSharedMemorySize, dynC);

    sort_kernel<<<1, NT, dynA>>>(score, box);
    mask_kernel<<<dim3(32, 128), 256>>>();
    sweep_kernel<<<1, 256, dynC>>>(box, out);
}

// round 15
// speedup vs baseline: 1.6569x; 1.0065x over previous
#include <cuda_runtime.h>
#include <cstdint>

#define N_BOX     8192
#define MAX_KEEP  256
#define MIN_SCORE 0.3f
#define NMS_THR   0.3f
#define NT        1024
#define NBKT      4096
#define NCHUNK    128          // 64-bit words per mask row (8192/64)
#define FULL      0xFFFFFFFFu

// ---------------- global scratch (static __device__, no allocation) ----------------
__device__ unsigned long long g_key[N_BOX];        // sorted keys (~score_bits, idx)
__device__ float4             g_cbox[N_BOX];       // sorted xyxy boxes
__device__ unsigned long long g_mask[N_BOX * NCHUNK];  // 8 MB suppression bitmask
__device__ unsigned long long g_diag[N_BOX];       // compact diagonal words (coalesced)
__device__ int                g_nval;

// ================= kernel A: bucket sort (exact stable descending) — R9 proven =================
extern __shared__ unsigned char dynsmem[];

__global__ void __launch_bounds__(NT, 1)
sort_kernel(const float* __restrict__ score, const float* __restrict__ box)
{
    unsigned long long* s_key = (unsigned long long*)dynsmem;          // 64 KB
    unsigned int*       s_cnt = (unsigned int*)(dynsmem + 65536);      // 16 KB
    unsigned int*       s_off = (unsigned int*)(dynsmem + 81920);      // 16 KB
    __shared__ unsigned int s_wsum[32];
    __shared__ int s_nvalid;

    const int tid  = threadIdx.x;
    const int lane = tid & 31;
    const int wid  = tid >> 5;

    for (int i = tid; i < NBKT; i += NT) s_cnt[i] = 0;
    __syncthreads();

    float sc[8]; int bk[8];
    #pragma unroll
    for (int k = 0; k < 8; k++) {
        int i = tid + k * NT;
        float s = score[i];
        sc[k] = s;
        int b = -1;
        if (s >= MIN_SCORE) {
            b = 4095 - min(4095, (int)(s * 4096.0f));   // score desc -> bucket asc (monotone)
            atomicAdd(&s_cnt[b], 1u);
        }
        bk[k] = b;
    }
    __syncthreads();

    unsigned int c0 = s_cnt[tid*4+0], c1 = s_cnt[tid*4+1], c2 = s_cnt[tid*4+2], c3 = s_cnt[tid*4+3];
    unsigned int tsum = c0 + c1 + c2 + c3;
    unsigned int p = tsum;
    #pragma unroll
    for (int d = 1; d < 32; d <<= 1) {
        unsigned int v = __shfl_up_sync(FULL, p, d);
        if (lane >= d) p += v;
    }
    if (lane == 31) s_wsum[wid] = p;
    __syncthreads();
    if (wid == 0) {
        unsigned int w = s_wsum[lane];
        unsigned int q = w;
        #pragma unroll
        for (int d = 1; d < 32; d <<= 1) {
            unsigned int v = __shfl_up_sync(FULL, q, d);
            if (lane >= d) q += v;
        }
        s_wsum[lane] = q - w;
        if (lane == 31) s_nvalid = (int)q;
    }
    __syncthreads();
    unsigned int basep = s_wsum[wid] + (p - tsum);
    s_off[tid*4+0] = basep;
    s_off[tid*4+1] = basep + c0;
    s_off[tid*4+2] = basep + c0 + c1;
    s_off[tid*4+3] = basep + c0 + c1 + c2;
    __syncthreads();

    #pragma unroll
    for (int k = 0; k < 8; k++) {
        if (bk[k] >= 0) {
            int i = tid + k * NT;
            unsigned int pos = atomicAdd(&s_off[bk[k]], 1u);
            s_key[pos] = ((unsigned long long)(~__float_as_uint(sc[k])) << 32) | (unsigned int)i;
        }
    }
    __syncthreads();

    // intra-bucket insertion sort on full u64 key (exact total order)
    for (int b = tid; b < NBKT; b += NT) {
        int lo = b ? (int)s_off[b-1] : 0;
        int hi = (int)s_off[b];
        for (int i = lo + 1; i < hi; i++) {
            unsigned long long v = s_key[i];
            int j = i - 1;
            while (j >= lo && s_key[j] > v) { s_key[j+1] = s_key[j]; j--; }
            s_key[j+1] = v;
        }
    }
    __syncthreads();

    const int nval = s_nvalid;
    for (int c = tid; c < nval; c += NT) {
        unsigned long long key = s_key[c];
        g_key[c] = key;
        int idx = (int)(key & 0xFFFFFFFFull);
        float4 b4 = *(const float4*)(box + idx * 16);
        float hw = b4.z * 0.5f, hh = b4.w * 0.5f;
        g_cbox[c] = make_float4(b4.x - hw, b4.y - hh, b4.x + hw, b4.y + hh);
    }
    if (tid == 0) g_nval = nval;
}

// ================= kernel B: suppression bitmask matrix — wide row tiles =================
// grid (8, 128): (row tile of 1024, col word); block = 1024 threads, one row each.
// Per-thread work identical to the proven R9 kernel (64-pair loop); only the
// block/tile geometry changes, amortizing tile fill + block overhead 4x.
// Division-free threshold test, bit-exact vs reference (guarded multiply-compare with
// exact-division fallback only inside a +-1e-6 relative window around the threshold).
__global__ void __launch_bounds__(1024)
mask_kernel()
{
    const int tj = blockIdx.y;               // col word 0..127
    const int i0 = blockIdx.x * 1024;        // row tile base
    const int nval = g_nval;
    if (i0 >= nval) return;
    if (tj * 64 + 63 <= i0) return;          // whole tile has j <= all rows -> unread

    __shared__ float4 cb[64];
    __shared__ float  car[64];
    const int t = threadIdx.x;
    if (t < 64) {
        int j = tj * 64 + t;
        float4 b = (j < nval) ? g_cbox[j] : make_float4(0,0,0,0);
        cb[t]  = b;
        car[t] = (b.z - b.x) * (b.w - b.y);
    }
    __syncthreads();

    const int i = i0 + t;
    if (i >= nval) return;
    float4 B  = g_cbox[i];
    float  AR = (B.z - B.x) * (B.w - B.y);

    const int qlo  = max(0, i + 1 - tj * 64);             // strict j > i
    const int qmax = min(64, nval - tj * 64);
    unsigned long long w = 0;
    #pragma unroll 4
    for (int q = qlo; q < qmax; q++) {
        float4 b = cb[q];
        float lx = fmaxf(B.x, b.x), ly = fmaxf(B.y, b.y);
        float rx = fminf(B.z, b.z), ry = fminf(B.w, b.w);
        float inter = fmaxf(rx - lx, 0.0f) * fmaxf(ry - ly, 0.0f);
        float denom = ((AR + car[q]) - inter) + 1e-9f;    // reference association order
        float thr   = denom * NMS_THR;
        bool hit;
        if (inter > thr * 1.000001f)      hit = true;     // definitely above threshold
        else if (inter < thr * 0.999999f) hit = false;    // definitely below
        else                              hit = (inter / denom) > NMS_THR;  // exact (rare)
        if (hit) w |= 1ull << q;
    }
    g_mask[i * NCHUNK + tj] = w;
    if (tj == (i >> 6)) g_diag[i] = w;       // compact diagonal copy (coalesced sweep preload)
}

// ================= kernel C: skip-empty sweep with coalesced diag preload — R14 proven =================
__global__ void __launch_bounds__(256, 1)
sweep_kernel(const float* __restrict__ box, float* __restrict__ out)
{
    unsigned long long* diag = (unsigned long long*)dynsmem;   // 64 KB

    __shared__ unsigned long long rem[NCHUNK];
    __shared__ int klist[64];
    __shared__ int keptidx[MAX_KEEP];
    __shared__ int s_orig[MAX_KEEP];
    __shared__ int s_c, s_n, s_kc, s_next;

    const int tid    = threadIdx.x;
    const int nval   = g_nval;
    const int nchunk = (nval + 63) >> 6;

    // coalesced one-time preload of all diagonal words + clear rem
    for (int i = tid; i < nval; i += 256)
        diag[i] = g_diag[i];
    if (tid < NCHUNK) rem[tid] = 0ull;
    if (tid == 0) { s_kc = 0; s_next = 0; }
    __syncthreads();

    while (true) {
        // ---- thread 0: scan forward, skipping alive-empty chunks at smem cost ----
        if (tid == 0) {
            int c  = s_next;
            int kc = s_kc;
            int n  = 0;
            while (c < nchunk) {
                int rembits = nval - c * 64;
                unsigned long long validw = (rembits >= 64) ? ~0ull : ((1ull << rembits) - 1ull);
                unsigned long long alive = validw & ~rem[c];
                if (!alive) { c++; continue; }
                const unsigned long long* db = diag + c * 64;
                while (alive && kc < MAX_KEEP) {
                    int t = __ffsll((long long)alive) - 1;
                    keptidx[kc++] = c * 64 + t;
                    klist[n++] = t;
                    alive &= ~db[t];
                    alive &= ~(1ull << t);
                }
                break;
            }
            // if cap reached, nothing after this will be resolved -> no propagation needed
            if (kc >= MAX_KEEP) n = 0;
            s_c = c; s_n = n; s_kc = kc; s_next = c + 1;
        }
        __syncthreads();

        const int n = s_n;
        if (n == 0) break;                    // end of list or kept cap reached

        // ---- propagate the new kept rows into rem (256-wide, coalesced) ----
        const int c    = s_c;
        const int base = c * 64;
        for (int w = c + 1 + tid; w < nchunk; w += 256) {
            unsigned long long acc = 0;
            for (int q = 0; q < n; q++)
                acc |= g_mask[(base + klist[q]) * NCHUNK + w];
            rem[w] |= acc;
        }
        __syncthreads();                      // rem complete before next scan
    }

    // ---------------- outputs ----------------
    // layout: [0,256) score | [256,4352) box (256x16) | [4352,4608) valid
    const int kc = s_kc;
    for (int k = tid; k < MAX_KEEP; k += 256) {
        if (k < kc) {
            unsigned long long key = g_key[keptidx[k]];
            s_orig[k]     = (int)(key & 0xFFFFFFFFull);
            out[k]        = __uint_as_float(~(unsigned int)(key >> 32));
            out[4352 + k] = 1.0f;
        } else {
            out[k]        = 0.0f;
            out[4352 + k] = 0.0f;
        }
    }
    __syncthreads();
    for (int e = tid; e < MAX_KEEP * 16; e += 256) {
        int k = e >> 4, c = e & 15;
        out[256 + e] = (k < kc) ? box[s_orig[k] * 16 + c] : 0.0f;
    }
}

// ---------------- launch ----------------
extern "C" void kernel_launch(void* const* d_in, const int* in_sizes, int n_in,
                              void* d_out, int out_size) {
    const float* score = (const float*)d_in[0];
    const float* box   = (const float*)d_in[1];
    float* out = (float*)d_out;

    const int dynA = 98304;   // 64K keys + 16K hist + 16K offsets
    cudaFuncSetAttribute(sort_kernel,
                         cudaFuncAttributeMaxDynamicSharedMemorySize, dynA);
    const int dynC = 65536;   // 64K diag
    cudaFuncSetAttribute(sweep_kernel,
                         cudaFuncAttributeMaxDynamicSharedMemorySize, dynC);

    sort_kernel<<<1, NT, dynA>>>(score, box);
    mask_kernel<<<dim3(8, 128), 1024>>>();
    sweep_kernel<<<1, 256, dynC>>>(box, out);
}